// round 15
// baseline (speedup 1.0000x reference)
#include <cuda_runtime.h>
#include <cuda_fp16.h>
#include <cstdint>

#define NTOK 8192
#define CDIM 1024
#define DDIM 64
#define BM 256
#define BN 128
#define SPLITS 4
#define KEYS_PER_SPLIT (NTOK / SPLITS)
#define CHUNKS (KEYS_PER_SPLIT / BN)
#define NTILES (NTOK / BM)

// q pre-scale: log2(e)/32 so S accumulators are base-2 exponents
#define QSCALE 0.045084220027780106f

// scratch (allocation-free)
__device__ __half g_qh[NTOK * DDIM];
__device__ __half g_kh[NTOK * DDIM];
__device__ __half g_vT[DDIM * NTOK];           // V^T, half [d][tok]
__device__ __half g_wh[192 * CDIM];            // [Wq|Wk|Wv] in half
__device__ float  g_po[SPLITS * NTOK * DDIM];  // partial O
__device__ float  g_pl[SPLITS * NTOK];         // partial l
__device__ int    g_cnt[NTILES];               // split-completion counters

// m16n8k16 fp16 HMMA, fp32 accumulate
__device__ __forceinline__ void mma_f16(float* c, const uint32_t* a,
                                        uint32_t b0, uint32_t b1) {
    asm volatile(
        "mma.sync.aligned.m16n8k16.row.col.f32.f16.f16.f32 "
        "{%0,%1,%2,%3}, {%4,%5,%6,%7}, {%8,%9}, {%0,%1,%2,%3};"
        : "+f"(c[0]), "+f"(c[1]), "+f"(c[2]), "+f"(c[3])
        : "r"(a[0]), "r"(a[1]), "r"(a[2]), "r"(a[3]), "r"(b0), "r"(b1));
}
__device__ __forceinline__ void ldsm_x4(uint32_t& r0, uint32_t& r1,
                                        uint32_t& r2, uint32_t& r3,
                                        const __half* p) {
    uint32_t a = (uint32_t)__cvta_generic_to_shared(p);
    asm volatile("ldmatrix.sync.aligned.m8n8.x4.shared.b16 {%0,%1,%2,%3}, [%4];"
                 : "=r"(r0), "=r"(r1), "=r"(r2), "=r"(r3) : "r"(a));
}
__device__ __forceinline__ void cp_async16(const void* smem_ptr, const void* gptr) {
    uint32_t sa = (uint32_t)__cvta_generic_to_shared(smem_ptr);
    asm volatile("cp.async.cg.shared.global [%0], [%1], 16;"
                 :: "r"(sa), "l"(gptr) : "memory");
}
#define CP_COMMIT() asm volatile("cp.async.commit_group;" ::: "memory")
#define CP_WAIT0()  asm volatile("cp.async.wait_group 0;" ::: "memory")
#define CP_WAIT1()  asm volatile("cp.async.wait_group 1;" ::: "memory")

__device__ __forceinline__ uint32_t h2(float a, float b) {
    __half2 h = __floats2half2_rn(a, b);
    return *(uint32_t*)&h;
}
__device__ __forceinline__ uint32_t ex2_f16x2(uint32_t a) {
    uint32_t d;
    asm("ex2.approx.f16x2 %0, %1;" : "=r"(d) : "r"(a));
    return d;
}

// ---------------------------------------------------------------------------
// Kernel 0: one-time W -> half conversion ([Wq|Wk|Wv] rows, 192x1024)
// ---------------------------------------------------------------------------
__global__ __launch_bounds__(256, 1) void wconv(
    const float* __restrict__ Wq, const float* __restrict__ Wk,
    const float* __restrict__ Wv)
{
    int idx  = blockIdx.x * 256 + threadIdx.x;   // 0..24575
    int base = idx * 8;
    int row  = base >> 10;
    int col  = base & 1023;
    const float* W = (row < 64) ? Wq + (size_t)row * CDIM
                   : (row < 128) ? Wk + (size_t)(row - 64) * CDIM
                                 : Wv + (size_t)(row - 128) * CDIM;
    float4 a = *(const float4*)(W + col);
    float4 b = *(const float4*)(W + col + 4);
    uint4 o;
    o.x = h2(a.x, a.y); o.y = h2(a.z, a.w);
    o.z = h2(b.x, b.y); o.w = h2(b.z, b.w);
    *(uint4*)(g_wh + base) = o;
}

// ---------------------------------------------------------------------------
// Kernel 1: QKV projection, fp16 MMA, K-chunks of 128 (unchanged from R14).
// ---------------------------------------------------------------------------
#define XP 136
#define XHB (64 * XP)
#define WSB (192 * XP)
#define QKV_SMEM_BYTES ((2 * XHB + 2 * WSB) * 2)

__global__ __launch_bounds__(256, 1) void qkv_mma(
    const float* __restrict__ x,
    const float* __restrict__ bq, const float* __restrict__ bk,
    const float* __restrict__ bv)
{
    extern __shared__ __half smq[];
    __half* xh = smq;
    __half* ws = smq + 2 * XHB;

    const int tid  = threadIdx.x;
    const int warp = tid >> 5;
    const int lane = tid & 31;
    const int r8   = lane & 7;
    const int hA   = (lane >> 3) & 1;
    const int hB   = lane >> 4;
    const int wm   = warp & 3;
    const int nh   = warp >> 2;
    const int row0 = blockIdx.x * 64;

    int xr[8], xc[8];
    const float* xptr[8];
#pragma unroll
    for (int i = 0; i < 8; i++) {
        int idx = i * 256 + tid;
        xr[i] = idx >> 5; xc[i] = (idx & 31) * 4;
        xptr[i] = x + (size_t)(row0 + xr[i]) * CDIM + xc[i];
    }
    int wr[12], wc8[12];
#pragma unroll
    for (int i = 0; i < 12; i++) {
        int idx = i * 256 + tid;
        wr[i] = idx >> 4; wc8[i] = (idx & 15) * 8;
    }

    float4 xreg[8];
#pragma unroll
    for (int i = 0; i < 8; i++) xreg[i] = *(const float4*)(xptr[i]);
#pragma unroll
    for (int i = 0; i < 12; i++)
        cp_async16(ws + wr[i] * XP + wc8[i], g_wh + (size_t)wr[i] * CDIM + wc8[i]);
    CP_COMMIT();

    float oacc[12][4];
#pragma unroll
    for (int n = 0; n < 12; n++)
#pragma unroll
        for (int j = 0; j < 4; j++) oacc[n][j] = 0.f;

    for (int kc = 0; kc < 8; kc++) {
        const int b = kc & 1;
#pragma unroll
        for (int i = 0; i < 8; i++) {
            float4 v = xreg[i];
            uint2 hi;
            hi.x = h2(v.x, v.y);
            hi.y = h2(v.z, v.w);
            *(uint2*)(xh + b * XHB + xr[i] * XP + xc[i]) = hi;
        }
        CP_WAIT0();
        __syncthreads();

        if (kc < 7) {
#pragma unroll
            for (int i = 0; i < 12; i++)
                cp_async16(ws + (b ^ 1) * WSB + wr[i] * XP + wc8[i],
                           g_wh + (size_t)wr[i] * CDIM + (kc + 1) * 128 + wc8[i]);
            CP_COMMIT();
#pragma unroll
            for (int i = 0; i < 8; i++)
                xreg[i] = *(const float4*)(xptr[i] + (kc + 1) * 128);
        }

        const __half* xb = xh + b * XHB;
        const __half* wb = ws + b * WSB;
#pragma unroll
        for (int kk = 0; kk < 8; kk++) {
            uint32_t ah[4];
            ldsm_x4(ah[0], ah[1], ah[2], ah[3],
                    xb + (wm * 16 + 8 * hA + r8) * XP + 16 * kk + 8 * hB);
#pragma unroll
            for (int np = 0; np < 6; np++) {
                uint32_t b00, b01, b10, b11;
                ldsm_x4(b00, b01, b10, b11,
                        wb + (nh * 96 + 16 * np + 8 * hB + r8) * XP
                           + 16 * kk + 8 * hA);
                mma_f16(oacc[2 * np],     ah, b00, b01);
                mma_f16(oacc[2 * np + 1], ah, b10, b11);
            }
        }
    }

    const int g  = lane >> 2;
    const int t4 = lane & 3;
    const int r0 = row0 + wm * 16 + g;
#pragma unroll
    for (int n = 0; n < 12; n++) {
        int cb = nh * 96 + 8 * n + 2 * t4;
        if (cb < 64) {
            float2 bias = *(const float2*)(bq + cb);
            *(uint32_t*)(g_qh + (size_t)r0 * DDIM + cb) =
                h2((oacc[n][0] + bias.x) * QSCALE, (oacc[n][1] + bias.y) * QSCALE);
            *(uint32_t*)(g_qh + (size_t)(r0 + 8) * DDIM + cb) =
                h2((oacc[n][2] + bias.x) * QSCALE, (oacc[n][3] + bias.y) * QSCALE);
        } else if (cb < 128) {
            int col = cb - 64;
            float2 bias = *(const float2*)(bk + col);
            *(uint32_t*)(g_kh + (size_t)r0 * DDIM + col) =
                h2(oacc[n][0] + bias.x, oacc[n][1] + bias.y);
            *(uint32_t*)(g_kh + (size_t)(r0 + 8) * DDIM + col) =
                h2(oacc[n][2] + bias.x, oacc[n][3] + bias.y);
        } else {
            int col = cb - 128;
            float bx = bv[col], by = bv[col + 1];
            g_vT[(size_t)col * NTOK + r0]           = __float2half_rn(oacc[n][0] + bx);
            g_vT[(size_t)(col + 1) * NTOK + r0]     = __float2half_rn(oacc[n][1] + by);
            g_vT[(size_t)col * NTOK + r0 + 8]       = __float2half_rn(oacc[n][2] + bx);
            g_vT[(size_t)(col + 1) * NTOK + r0 + 8] = __float2half_rn(oacc[n][3] + by);
        }
    }
}

// ---------------------------------------------------------------------------
// Kernel 2: fp16 flash attention + fused last-CTA merge.
// 256 thr = 8 warps x 32 rows; BM=256, SPLITS=4, grid (32,4)=128 CTAs.
// 3-stage cp.async pipeline; hoisted constant ones-fragment for l-MMA.
// smem (halfs): K[3][128*72] | V[3][80*136] (buffer 0 rows 64..79: ones+zeros)
// ---------------------------------------------------------------------------
#define KP 72
#define VP 136
#define KBUF (128 * KP)
#define VBUF (80 * VP)
#define HVBASE (3 * KBUF)
#define HEND (HVBASE + 3 * VBUF)
#define FLASH_SMEM_BYTES (HEND * 2 + 16)

__global__ __launch_bounds__(256, 1) void flash_mma(float* __restrict__ out)
{
    extern __shared__ __half smh[];
    int* smflag = (int*)(smh + HEND);

    const int tid   = threadIdx.x;
    const int warp  = tid >> 5;
    const int lane  = tid & 31;
    const int r8    = lane & 7;
    const int hA    = (lane >> 3) & 1;
    const int hB    = lane >> 4;
    const int g     = lane >> 2;
    const int t4    = lane & 3;
    const int wr0   = warp * 32;           // 32 rows per warp
    const int row0  = blockIdx.x * BM;
    const int split = blockIdx.y;
    const int key0  = split * KEYS_PER_SPLIT;

    // init ones/zero rows (64..79) of V buffer 0 only (constant fragment source)
    for (int i = tid; i < 16 * VP; i += 256) {
        int rr = i / VP, cc = i % VP;
        smh[HVBASE + (64 + rr) * VP + cc] =
            (rr == 0) ? __float2half(1.f) : __float2half(0.f);
    }
    __syncthreads();

    // hoisted constant ones-fragment (independent of j2/chunk)
    uint32_t wn0, wn1, wn2, wn3;
    ldsm_x4(wn0, wn1, wn2, wn3, smh + HVBASE + (64 + 8 * hB + r8) * VP + 8 * hA);

    // Q A-fragments for 2 m-tiles (pre-scaled by QSCALE)
    uint32_t aQ[2][4][4];
#pragma unroll
    for (int m = 0; m < 2; m++) {
        const __half* q0 = g_qh + (size_t)(row0 + wr0 + m * 16 + g) * DDIM;
        const __half* q1 = q0 + 8 * DDIM;
#pragma unroll
        for (int kk = 0; kk < 4; kk++) {
            int c0 = 16 * kk + 2 * t4;
            aQ[m][kk][0] = *(const uint32_t*)(q0 + c0);
            aQ[m][kk][1] = *(const uint32_t*)(q1 + c0);
            aQ[m][kk][2] = *(const uint32_t*)(q0 + c0 + 8);
            aQ[m][kk][3] = *(const uint32_t*)(q1 + c0 + 8);
        }
    }

    // staging coordinates: 4 K + 4 V cp.async16 per thread per chunk
    int kr[4], kc8[4], vr[4], vc8[4];
#pragma unroll
    for (int i = 0; i < 4; i++) {
        int idx = i * 256 + tid;
        kr[i] = idx >> 3;  kc8[i] = (idx & 7) * 8;
        vr[i] = idx >> 4;  vc8[i] = (idx & 15) * 8;
    }

    // prologue: issue chunks 0 and 1 (buffers 0, 1)
#pragma unroll
    for (int p = 0; p < 2; p++) {
        const size_t nb = (size_t)(key0 + p * BN);
        __half* kb = smh + p * KBUF;
        __half* vb = smh + HVBASE + p * VBUF;
#pragma unroll
        for (int i = 0; i < 4; i++) {
            cp_async16(kb + kr[i] * KP + kc8[i],
                       g_kh + (nb + kr[i]) * DDIM + kc8[i]);
            cp_async16(vb + vr[i] * VP + vc8[i],
                       g_vT + (size_t)vr[i] * NTOK + nb + vc8[i]);
        }
        CP_COMMIT();
    }

    float oacc[2][9][4];
#pragma unroll
    for (int m = 0; m < 2; m++)
#pragma unroll
        for (int n = 0; n < 9; n++)
#pragma unroll
            for (int j = 0; j < 4; j++) oacc[m][n][j] = 0.f;

    int buf = 0, nbuf = 2;
    for (int ch = 0; ch < CHUNKS; ch++) {
        CP_WAIT1();
        __syncthreads();

        if (ch + 2 < CHUNKS) {
            const size_t nb = (size_t)(key0 + (ch + 2) * BN);
            __half* kb = smh + nbuf * KBUF;
            __half* vb = smh + HVBASE + nbuf * VBUF;
#pragma unroll
            for (int i = 0; i < 4; i++) {
                cp_async16(kb + kr[i] * KP + kc8[i],
                           g_kh + (nb + kr[i]) * DDIM + kc8[i]);
                cp_async16(vb + vr[i] * VP + vc8[i],
                           g_vT + (size_t)vr[i] * NTOK + nb + vc8[i]);
            }
            CP_COMMIT();
        }

        const __half* Ks = smh + buf * KBUF;
        const __half* Vs = smh + HVBASE + buf * VBUF;

#pragma unroll
        for (int j2 = 0; j2 < 8; j2++) {
            float s[2][2][4];
#pragma unroll
            for (int m = 0; m < 2; m++)
#pragma unroll
                for (int q = 0; q < 2; q++)
#pragma unroll
                    for (int j = 0; j < 4; j++) s[m][q][j] = 0.f;
#pragma unroll
            for (int kk = 0; kk < 4; kk++) {
                uint32_t b00, b01, b10, b11;
                ldsm_x4(b00, b01, b10, b11,
                        Ks + (16 * j2 + 8 * hB + r8) * KP + 16 * kk + 8 * hA);
                mma_f16(s[0][0], aQ[0][kk], b00, b01);
                mma_f16(s[0][1], aQ[0][kk], b10, b11);
                mma_f16(s[1][0], aQ[1][kk], b00, b01);
                mma_f16(s[1][1], aQ[1][kk], b10, b11);
            }
            uint32_t aP[2][4];
#pragma unroll
            for (int m = 0; m < 2; m++) {
                aP[m][0] = ex2_f16x2(h2(s[m][0][0], s[m][0][1]));
                aP[m][1] = ex2_f16x2(h2(s[m][0][2], s[m][0][3]));
                aP[m][2] = ex2_f16x2(h2(s[m][1][0], s[m][1][1]));
                aP[m][3] = ex2_f16x2(h2(s[m][1][2], s[m][1][3]));
            }
#pragma unroll
            for (int np = 0; np < 4; np++) {
                uint32_t v00, v01, v10, v11;
                ldsm_x4(v00, v01, v10, v11,
                        Vs + (16 * np + 8 * hB + r8) * VP + 16 * j2 + 8 * hA);
                mma_f16(oacc[0][2 * np],     aP[0], v00, v01);
                mma_f16(oacc[0][2 * np + 1], aP[0], v10, v11);
                mma_f16(oacc[1][2 * np],     aP[1], v00, v01);
                mma_f16(oacc[1][2 * np + 1], aP[1], v10, v11);
            }
            // l += P @ ones (constant hoisted fragment)
            mma_f16(oacc[0][8], aP[0], wn0, wn1);
            mma_f16(oacc[1][8], aP[1], wn0, wn1);
        }

        buf  = (buf  + 1 == 3) ? 0 : buf + 1;
        nbuf = (nbuf + 1 == 3) ? 0 : nbuf + 1;
    }

    // epilogue: write partial O and l for both m-tiles
#pragma unroll
    for (int m = 0; m < 2; m++) {
        const size_t r0 = (size_t)split * NTOK + row0 + wr0 + m * 16 + g;
        const size_t r1 = r0 + 8;
#pragma unroll
        for (int n = 0; n < 8; n++) {
            int col = 8 * n + 2 * t4;
            *(float2*)(g_po + r0 * DDIM + col) =
                make_float2(oacc[m][n][0], oacc[m][n][1]);
            *(float2*)(g_po + r1 * DDIM + col) =
                make_float2(oacc[m][n][2], oacc[m][n][3]);
        }
        if (t4 == 0) {
            g_pl[r0] = oacc[m][8][0];
            g_pl[r1] = oacc[m][8][2];
        }
    }

    // --- fused merge: last split-CTA of this row tile normalizes + writes ---
    __threadfence();       // make this CTA's po/pl globally visible
    __syncthreads();       // all threads' fences done before the atomic
    if (tid == 0)
        *smflag = atomicAdd(&g_cnt[blockIdx.x], 1);
    __syncthreads();
    if (*smflag != SPLITS - 1) return;
    __threadfence();       // acquire: other CTAs' po/pl now visible

    // doer: 16 passes x (16 rows x 16 col-threads), coalesced 256B segments
#pragma unroll 1
    for (int p = 0; p < 16; p++) {
        int row = row0 + p * 16 + (tid >> 4);
        int cg  = (tid & 15) * 4;
        float l = g_pl[row] + g_pl[NTOK + row]
                + g_pl[2 * NTOK + row] + g_pl[3 * NTOK + row];
        float inv = 1.f / l;
        float4 a = __ldcg((const float4*)(g_po + (size_t)row * DDIM + cg));
        float4 b = __ldcg((const float4*)(g_po + ((size_t)NTOK + row) * DDIM + cg));
        float4 c = __ldcg((const float4*)(g_po + ((size_t)2 * NTOK + row) * DDIM + cg));
        float4 d = __ldcg((const float4*)(g_po + ((size_t)3 * NTOK + row) * DDIM + cg));
        float4 y = make_float4((a.x + b.x + c.x + d.x) * inv,
                               (a.y + b.y + c.y + d.y) * inv,
                               (a.z + b.z + c.z + d.z) * inv,
                               (a.w + b.w + c.w + d.w) * inv);
        float* op = out + (size_t)row * 1024 + cg;
#pragma unroll
        for (int h = 0; h < 16; h++)
            __stcs((float4*)(op + h * 64), y);
    }
    // reset counter for the next graph replay
    __syncthreads();
    if (tid == 0) g_cnt[blockIdx.x] = 0;
}

// ---------------------------------------------------------------------------
extern "C" void kernel_launch(void* const* d_in, const int* in_sizes, int n_in,
                              void* d_out, int out_size)
{
    const float* x  = (const float*)d_in[0];
    const float* Wq = (const float*)d_in[1];
    const float* bq = (const float*)d_in[2];
    const float* Wk = (const float*)d_in[3];
    const float* bk = (const float*)d_in[4];
    const float* Wv = (const float*)d_in[5];
    const float* bv = (const float*)d_in[6];
    float* out = (float*)d_out;

    wconv<<<96, 256>>>(Wq, Wk, Wv);

    cudaFuncSetAttribute(qkv_mma, cudaFuncAttributeMaxDynamicSharedMemorySize,
                         QKV_SMEM_BYTES);
    qkv_mma<<<128, 256, QKV_SMEM_BYTES>>>(x, bq, bk, bv);

    cudaFuncSetAttribute(flash_mma, cudaFuncAttributeMaxDynamicSharedMemorySize,
                         FLASH_SMEM_BYTES);
    flash_mma<<<dim3(32, 4), 256, FLASH_SMEM_BYTES>>>(out);
}

// round 16
// speedup vs baseline: 1.2387x; 1.2387x over previous
#include <cuda_runtime.h>
#include <cuda_fp16.h>
#include <cstdint>

#define NTOK 8192
#define CDIM 1024
#define DDIM 64
#define BM 256
#define BN 128
#define SPLITS 4
#define KEYS_PER_SPLIT (NTOK / SPLITS)
#define CHUNKS (KEYS_PER_SPLIT / BN)

// q pre-scale: log2(e)/32 so S accumulators are base-2 exponents
#define QSCALE 0.045084220027780106f

// scratch (allocation-free)
__device__ __half g_qh[NTOK * DDIM];
__device__ __half g_kh[NTOK * DDIM];
__device__ __half g_vT[DDIM * NTOK];           // V^T, half [d][tok]
__device__ __half g_wh[192 * CDIM];            // [Wq|Wk|Wv] in half
__device__ float  g_po[SPLITS * NTOK * DDIM];  // partial O
__device__ float  g_pl[SPLITS * NTOK];         // partial l

// m16n8k16 fp16 HMMA, fp32 accumulate
__device__ __forceinline__ void mma_f16(float* c, const uint32_t* a,
                                        uint32_t b0, uint32_t b1) {
    asm volatile(
        "mma.sync.aligned.m16n8k16.row.col.f32.f16.f16.f32 "
        "{%0,%1,%2,%3}, {%4,%5,%6,%7}, {%8,%9}, {%0,%1,%2,%3};"
        : "+f"(c[0]), "+f"(c[1]), "+f"(c[2]), "+f"(c[3])
        : "r"(a[0]), "r"(a[1]), "r"(a[2]), "r"(a[3]), "r"(b0), "r"(b1));
}
__device__ __forceinline__ void ldsm_x4(uint32_t& r0, uint32_t& r1,
                                        uint32_t& r2, uint32_t& r3,
                                        const __half* p) {
    uint32_t a = (uint32_t)__cvta_generic_to_shared(p);
    asm volatile("ldmatrix.sync.aligned.m8n8.x4.shared.b16 {%0,%1,%2,%3}, [%4];"
                 : "=r"(r0), "=r"(r1), "=r"(r2), "=r"(r3) : "r"(a));
}
__device__ __forceinline__ void cp_async16(const void* smem_ptr, const void* gptr) {
    uint32_t sa = (uint32_t)__cvta_generic_to_shared(smem_ptr);
    asm volatile("cp.async.cg.shared.global [%0], [%1], 16;"
                 :: "r"(sa), "l"(gptr) : "memory");
}
#define CP_COMMIT() asm volatile("cp.async.commit_group;" ::: "memory")
#define CP_WAIT0()  asm volatile("cp.async.wait_group 0;" ::: "memory")
#define CP_WAIT1()  asm volatile("cp.async.wait_group 1;" ::: "memory")

__device__ __forceinline__ uint32_t h2(float a, float b) {
    __half2 h = __floats2half2_rn(a, b);
    return *(uint32_t*)&h;
}
__device__ __forceinline__ uint32_t ex2_f16x2(uint32_t a) {
    uint32_t d;
    asm("ex2.approx.f16x2 %0, %1;" : "=r"(d) : "r"(a));
    return d;
}

// ---------------------------------------------------------------------------
// Kernel 0: one-time W -> half conversion ([Wq|Wk|Wv] rows, 192x1024)
// grid 192 x 256, 4 elements per thread (latency-bound; more threads)
// ---------------------------------------------------------------------------
__global__ __launch_bounds__(256, 1) void wconv(
    const float* __restrict__ Wq, const float* __restrict__ Wk,
    const float* __restrict__ Wv)
{
    int idx  = blockIdx.x * 256 + threadIdx.x;   // 0..49151
    int base = idx * 4;
    int row  = base >> 10;
    int col  = base & 1023;
    const float* W = (row < 64) ? Wq + (size_t)row * CDIM
                   : (row < 128) ? Wk + (size_t)(row - 64) * CDIM
                                 : Wv + (size_t)(row - 128) * CDIM;
    float4 a = *(const float4*)(W + col);
    uint2 o;
    o.x = h2(a.x, a.y); o.y = h2(a.z, a.w);
    *(uint2*)(g_wh + base) = o;
}

// ---------------------------------------------------------------------------
// Kernel 1: QKV projection, fp16 MMA, K-chunks of 128 (unchanged from R14).
// ---------------------------------------------------------------------------
#define XP 136
#define XHB (64 * XP)
#define WSB (192 * XP)
#define QKV_SMEM_BYTES ((2 * XHB + 2 * WSB) * 2)

__global__ __launch_bounds__(256, 1) void qkv_mma(
    const float* __restrict__ x,
    const float* __restrict__ bq, const float* __restrict__ bk,
    const float* __restrict__ bv)
{
    extern __shared__ __half smq[];
    __half* xh = smq;
    __half* ws = smq + 2 * XHB;

    const int tid  = threadIdx.x;
    const int warp = tid >> 5;
    const int lane = tid & 31;
    const int r8   = lane & 7;
    const int hA   = (lane >> 3) & 1;
    const int hB   = lane >> 4;
    const int wm   = warp & 3;
    const int nh   = warp >> 2;
    const int row0 = blockIdx.x * 64;

    int xr[8], xc[8];
    const float* xptr[8];
#pragma unroll
    for (int i = 0; i < 8; i++) {
        int idx = i * 256 + tid;
        xr[i] = idx >> 5; xc[i] = (idx & 31) * 4;
        xptr[i] = x + (size_t)(row0 + xr[i]) * CDIM + xc[i];
    }
    int wr[12], wc8[12];
#pragma unroll
    for (int i = 0; i < 12; i++) {
        int idx = i * 256 + tid;
        wr[i] = idx >> 4; wc8[i] = (idx & 15) * 8;
    }

    float4 xreg[8];
#pragma unroll
    for (int i = 0; i < 8; i++) xreg[i] = *(const float4*)(xptr[i]);
#pragma unroll
    for (int i = 0; i < 12; i++)
        cp_async16(ws + wr[i] * XP + wc8[i], g_wh + (size_t)wr[i] * CDIM + wc8[i]);
    CP_COMMIT();

    float oacc[12][4];
#pragma unroll
    for (int n = 0; n < 12; n++)
#pragma unroll
        for (int j = 0; j < 4; j++) oacc[n][j] = 0.f;

    for (int kc = 0; kc < 8; kc++) {
        const int b = kc & 1;
#pragma unroll
        for (int i = 0; i < 8; i++) {
            float4 v = xreg[i];
            uint2 hi;
            hi.x = h2(v.x, v.y);
            hi.y = h2(v.z, v.w);
            *(uint2*)(xh + b * XHB + xr[i] * XP + xc[i]) = hi;
        }
        CP_WAIT0();
        __syncthreads();

        if (kc < 7) {
#pragma unroll
            for (int i = 0; i < 12; i++)
                cp_async16(ws + (b ^ 1) * WSB + wr[i] * XP + wc8[i],
                           g_wh + (size_t)wr[i] * CDIM + (kc + 1) * 128 + wc8[i]);
            CP_COMMIT();
#pragma unroll
            for (int i = 0; i < 8; i++)
                xreg[i] = *(const float4*)(xptr[i] + (kc + 1) * 128);
        }

        const __half* xb = xh + b * XHB;
        const __half* wb = ws + b * WSB;
#pragma unroll
        for (int kk = 0; kk < 8; kk++) {
            uint32_t ah[4];
            ldsm_x4(ah[0], ah[1], ah[2], ah[3],
                    xb + (wm * 16 + 8 * hA + r8) * XP + 16 * kk + 8 * hB);
#pragma unroll
            for (int np = 0; np < 6; np++) {
                uint32_t b00, b01, b10, b11;
                ldsm_x4(b00, b01, b10, b11,
                        wb + (nh * 96 + 16 * np + 8 * hB + r8) * XP
                           + 16 * kk + 8 * hA);
                mma_f16(oacc[2 * np],     ah, b00, b01);
                mma_f16(oacc[2 * np + 1], ah, b10, b11);
            }
        }
    }

    const int g  = lane >> 2;
    const int t4 = lane & 3;
    const int r0 = row0 + wm * 16 + g;
#pragma unroll
    for (int n = 0; n < 12; n++) {
        int cb = nh * 96 + 8 * n + 2 * t4;
        if (cb < 64) {
            float2 bias = *(const float2*)(bq + cb);
            *(uint32_t*)(g_qh + (size_t)r0 * DDIM + cb) =
                h2((oacc[n][0] + bias.x) * QSCALE, (oacc[n][1] + bias.y) * QSCALE);
            *(uint32_t*)(g_qh + (size_t)(r0 + 8) * DDIM + cb) =
                h2((oacc[n][2] + bias.x) * QSCALE, (oacc[n][3] + bias.y) * QSCALE);
        } else if (cb < 128) {
            int col = cb - 64;
            float2 bias = *(const float2*)(bk + col);
            *(uint32_t*)(g_kh + (size_t)r0 * DDIM + col) =
                h2(oacc[n][0] + bias.x, oacc[n][1] + bias.y);
            *(uint32_t*)(g_kh + (size_t)(r0 + 8) * DDIM + col) =
                h2(oacc[n][2] + bias.x, oacc[n][3] + bias.y);
        } else {
            int col = cb - 128;
            float bx = bv[col], by = bv[col + 1];
            g_vT[(size_t)col * NTOK + r0]           = __float2half_rn(oacc[n][0] + bx);
            g_vT[(size_t)(col + 1) * NTOK + r0]     = __float2half_rn(oacc[n][1] + by);
            g_vT[(size_t)col * NTOK + r0 + 8]       = __float2half_rn(oacc[n][2] + bx);
            g_vT[(size_t)(col + 1) * NTOK + r0 + 8] = __float2half_rn(oacc[n][3] + by);
        }
    }
}

// ---------------------------------------------------------------------------
// Kernel 2: fp16 flash attention (R14 pipeline + hoisted ones-fragment).
// 256 thr = 8 warps x 32 rows; BM=256, SPLITS=4, grid (32,4)=128 CTAs.
// smem (halfs): K[3][128*72] | V[3][80*136] (buffer 0 rows 64..79: ones+zeros)
// ---------------------------------------------------------------------------
#define KP 72
#define VP 136
#define KBUF (128 * KP)
#define VBUF (80 * VP)
#define HVBASE (3 * KBUF)
#define HEND (HVBASE + 3 * VBUF)
#define FLASH_SMEM_BYTES (HEND * 2)

__global__ __launch_bounds__(256, 1) void flash_mma()
{
    extern __shared__ __half smh[];

    const int tid   = threadIdx.x;
    const int warp  = tid >> 5;
    const int lane  = tid & 31;
    const int r8    = lane & 7;
    const int hA    = (lane >> 3) & 1;
    const int hB    = lane >> 4;
    const int g     = lane >> 2;
    const int t4    = lane & 3;
    const int wr0   = warp * 32;           // 32 rows per warp
    const int row0  = blockIdx.x * BM;
    const int split = blockIdx.y;
    const int key0  = split * KEYS_PER_SPLIT;

    // init ones/zero rows (64..79) of V buffer 0 (constant fragment source)
    for (int i = tid; i < 16 * VP; i += 256) {
        int rr = i / VP, cc = i % VP;
        smh[HVBASE + (64 + rr) * VP + cc] =
            (rr == 0) ? __float2half(1.f) : __float2half(0.f);
    }
    __syncthreads();

    // hoisted constant ones-fragment (independent of j2/chunk)
    uint32_t wn0, wn1, wn2, wn3;
    ldsm_x4(wn0, wn1, wn2, wn3, smh + HVBASE + (64 + 8 * hB + r8) * VP + 8 * hA);

    // Q A-fragments for 2 m-tiles (pre-scaled by QSCALE)
    uint32_t aQ[2][4][4];
#pragma unroll
    for (int m = 0; m < 2; m++) {
        const __half* q0 = g_qh + (size_t)(row0 + wr0 + m * 16 + g) * DDIM;
        const __half* q1 = q0 + 8 * DDIM;
#pragma unroll
        for (int kk = 0; kk < 4; kk++) {
            int c0 = 16 * kk + 2 * t4;
            aQ[m][kk][0] = *(const uint32_t*)(q0 + c0);
            aQ[m][kk][1] = *(const uint32_t*)(q1 + c0);
            aQ[m][kk][2] = *(const uint32_t*)(q0 + c0 + 8);
            aQ[m][kk][3] = *(const uint32_t*)(q1 + c0 + 8);
        }
    }

    // staging coordinates: 4 K + 4 V cp.async16 per thread per chunk
    int kr[4], kc8[4], vr[4], vc8[4];
#pragma unroll
    for (int i = 0; i < 4; i++) {
        int idx = i * 256 + tid;
        kr[i] = idx >> 3;  kc8[i] = (idx & 7) * 8;
        vr[i] = idx >> 4;  vc8[i] = (idx & 15) * 8;
    }

    // prologue: issue chunks 0 and 1 (buffers 0, 1)
#pragma unroll
    for (int p = 0; p < 2; p++) {
        const size_t nb = (size_t)(key0 + p * BN);
        __half* kb = smh + p * KBUF;
        __half* vb = smh + HVBASE + p * VBUF;
#pragma unroll
        for (int i = 0; i < 4; i++) {
            cp_async16(kb + kr[i] * KP + kc8[i],
                       g_kh + (nb + kr[i]) * DDIM + kc8[i]);
            cp_async16(vb + vr[i] * VP + vc8[i],
                       g_vT + (size_t)vr[i] * NTOK + nb + vc8[i]);
        }
        CP_COMMIT();
    }

    float oacc[2][9][4];
#pragma unroll
    for (int m = 0; m < 2; m++)
#pragma unroll
        for (int n = 0; n < 9; n++)
#pragma unroll
            for (int j = 0; j < 4; j++) oacc[m][n][j] = 0.f;

    int buf = 0, nbuf = 2;
    for (int ch = 0; ch < CHUNKS; ch++) {
        CP_WAIT1();
        __syncthreads();

        if (ch + 2 < CHUNKS) {
            const size_t nb = (size_t)(key0 + (ch + 2) * BN);
            __half* kb = smh + nbuf * KBUF;
            __half* vb = smh + HVBASE + nbuf * VBUF;
#pragma unroll
            for (int i = 0; i < 4; i++) {
                cp_async16(kb + kr[i] * KP + kc8[i],
                           g_kh + (nb + kr[i]) * DDIM + kc8[i]);
                cp_async16(vb + vr[i] * VP + vc8[i],
                           g_vT + (size_t)vr[i] * NTOK + nb + vc8[i]);
            }
            CP_COMMIT();
        }

        const __half* Ks = smh + buf * KBUF;
        const __half* Vs = smh + HVBASE + buf * VBUF;

#pragma unroll
        for (int j2 = 0; j2 < 8; j2++) {
            float s[2][2][4];
#pragma unroll
            for (int m = 0; m < 2; m++)
#pragma unroll
                for (int q = 0; q < 2; q++)
#pragma unroll
                    for (int j = 0; j < 4; j++) s[m][q][j] = 0.f;
#pragma unroll
            for (int kk = 0; kk < 4; kk++) {
                uint32_t b00, b01, b10, b11;
                ldsm_x4(b00, b01, b10, b11,
                        Ks + (16 * j2 + 8 * hB + r8) * KP + 16 * kk + 8 * hA);
                mma_f16(s[0][0], aQ[0][kk], b00, b01);
                mma_f16(s[0][1], aQ[0][kk], b10, b11);
                mma_f16(s[1][0], aQ[1][kk], b00, b01);
                mma_f16(s[1][1], aQ[1][kk], b10, b11);
            }
            uint32_t aP[2][4];
#pragma unroll
            for (int m = 0; m < 2; m++) {
                aP[m][0] = ex2_f16x2(h2(s[m][0][0], s[m][0][1]));
                aP[m][1] = ex2_f16x2(h2(s[m][0][2], s[m][0][3]));
                aP[m][2] = ex2_f16x2(h2(s[m][1][0], s[m][1][1]));
                aP[m][3] = ex2_f16x2(h2(s[m][1][2], s[m][1][3]));
            }
#pragma unroll
            for (int np = 0; np < 4; np++) {
                uint32_t v00, v01, v10, v11;
                ldsm_x4(v00, v01, v10, v11,
                        Vs + (16 * np + 8 * hB + r8) * VP + 16 * j2 + 8 * hA);
                mma_f16(oacc[0][2 * np],     aP[0], v00, v01);
                mma_f16(oacc[0][2 * np + 1], aP[0], v10, v11);
                mma_f16(oacc[1][2 * np],     aP[1], v00, v01);
                mma_f16(oacc[1][2 * np + 1], aP[1], v10, v11);
            }
            // l += P @ ones (constant hoisted fragment)
            mma_f16(oacc[0][8], aP[0], wn0, wn1);
            mma_f16(oacc[1][8], aP[1], wn0, wn1);
        }

        buf  = (buf  + 1 == 3) ? 0 : buf + 1;
        nbuf = (nbuf + 1 == 3) ? 0 : nbuf + 1;
    }

    // epilogue: write partial O and l for both m-tiles
#pragma unroll
    for (int m = 0; m < 2; m++) {
        const size_t r0 = (size_t)split * NTOK + row0 + wr0 + m * 16 + g;
        const size_t r1 = r0 + 8;
#pragma unroll
        for (int n = 0; n < 8; n++) {
            int col = 8 * n + 2 * t4;
            *(float2*)(g_po + r0 * DDIM + col) =
                make_float2(oacc[m][n][0], oacc[m][n][1]);
            *(float2*)(g_po + r1 * DDIM + col) =
                make_float2(oacc[m][n][2], oacc[m][n][3]);
        }
        if (t4 == 0) {
            g_pl[r0] = oacc[m][8][0];
            g_pl[r1] = oacc[m][8][2];
        }
    }
}

// ---------------------------------------------------------------------------
// Kernel 3: merge 4 split-KV partials, write 16x-tiled output.
// ---------------------------------------------------------------------------
__global__ __launch_bounds__(256, 1) void merge_kernel(float* __restrict__ out)
{
    int g   = blockIdx.x * 256 + threadIdx.x;   // 0..262143
    int row = g >> 5;
    int sub = (g >> 4) & 1;
    int cg  = (g & 15) * 4;
    float l = g_pl[row] + g_pl[NTOK + row]
            + g_pl[2 * NTOK + row] + g_pl[3 * NTOK + row];
    float inv = 1.f / l;
    float4 a = *(const float4*)(g_po + (size_t)row * DDIM + cg);
    float4 b = *(const float4*)(g_po + ((size_t)NTOK + row) * DDIM + cg);
    float4 c = *(const float4*)(g_po + ((size_t)2 * NTOK + row) * DDIM + cg);
    float4 d = *(const float4*)(g_po + ((size_t)3 * NTOK + row) * DDIM + cg);
    float4 y = make_float4((a.x + b.x + c.x + d.x) * inv,
                           (a.y + b.y + c.y + d.y) * inv,
                           (a.z + b.z + c.z + d.z) * inv,
                           (a.w + b.w + c.w + d.w) * inv);
    float* op = out + (size_t)row * 1024 + sub * 512 + cg;
#pragma unroll
    for (int h = 0; h < 8; h++)
        __stcs((float4*)(op + h * 64), y);
}

// ---------------------------------------------------------------------------
extern "C" void kernel_launch(void* const* d_in, const int* in_sizes, int n_in,
                              void* d_out, int out_size)
{
    const float* x  = (const float*)d_in[0];
    const float* Wq = (const float*)d_in[1];
    const float* bq = (const float*)d_in[2];
    const float* Wk = (const float*)d_in[3];
    const float* bk = (const float*)d_in[4];
    const float* Wv = (const float*)d_in[5];
    const float* bv = (const float*)d_in[6];
    float* out = (float*)d_out;

    wconv<<<192, 256>>>(Wq, Wk, Wv);

    cudaFuncSetAttribute(qkv_mma, cudaFuncAttributeMaxDynamicSharedMemorySize,
                         QKV_SMEM_BYTES);
    qkv_mma<<<128, 256, QKV_SMEM_BYTES>>>(x, bq, bk, bv);

    cudaFuncSetAttribute(flash_mma, cudaFuncAttributeMaxDynamicSharedMemorySize,
                         FLASH_SMEM_BYTES);
    flash_mma<<<dim3(32, 4), 256, FLASH_SMEM_BYTES>>>();

    merge_kernel<<<1024, 256>>>(out);
}